// round 5
// baseline (speedup 1.0000x reference)
#include <cuda_runtime.h>
#include <cstdint>
#include <cstddef>

#define N_NODES 8192
#define DIN     512
#define DOUT    256
#define ALPHA   0.2f
#define NEG_INF -9e15f
#define L2E     1.4426950408889634f

// ---------------- scratch (device globals; no allocations allowed) ----------
__device__ float    g_Wh [(size_t)N_NODES * DOUT];   // 8 MB fp32 row-major (k2)
__device__ uint32_t g_WhB[(size_t)DOUT * N_NODES];   // 8 MB tf32, B-fragment order (k4)
__device__ float g_src[N_NODES];
__device__ float g_dst[N_NODES];
__device__ float g_rmax[N_NODES];
__device__ float g_rsum[N_NODES];

// ---------------- helpers ----------------------------------------------------
__device__ __forceinline__ uint32_t f2tf32(float x) {
    uint32_t r;
    asm("cvt.rna.tf32.f32 %0, %1;" : "=r"(r) : "f"(x));
    return r;
}

__device__ __forceinline__ void mma_tf32(float* c,
                                         uint32_t a0, uint32_t a1, uint32_t a2, uint32_t a3,
                                         uint32_t b0, uint32_t b1) {
    asm volatile(
        "mma.sync.aligned.m16n8k8.row.col.f32.tf32.tf32.f32 "
        "{%0,%1,%2,%3}, {%4,%5,%6,%7}, {%8,%9}, {%0,%1,%2,%3};\n"
        : "+f"(c[0]), "+f"(c[1]), "+f"(c[2]), "+f"(c[3])
        : "r"(a0), "r"(a1), "r"(a2), "r"(a3), "r"(b0), "r"(b1));
}

__device__ __forceinline__ void cp_async16(uint32_t smem_addr, const void* gptr) {
    asm volatile("cp.async.cg.shared.global [%0], [%1], 16;\n"
                 :: "r"(smem_addr), "l"(gptr));
}
__device__ __forceinline__ void cp_commit() {
    asm volatile("cp.async.commit_group;\n" ::: "memory");
}
template <int N>
__device__ __forceinline__ void cp_wait() {
    asm volatile("cp.async.wait_group %0;\n" :: "n"(N) : "memory");
}

// ---------------- K1: Wh = X @ W  (fp32, tiled) ------------------------------
// Also emits g_WhB: tf32 bits in the exact B-fragment order k4 consumes.
// B-frag index for value (n, m): jq=n>>6, kt=m>>5, kk=(m&31)>>3, ntile=(n&63)>>3,
// lane=((n&7)<<2)|(m&3), reg=(m&4)>>2 ->
// idx = (((jq*256+kt)*4+kk)*8+ntile)*64 + lane*2 + reg
__global__ void __launch_bounds__(256) k1_gemm(const float* __restrict__ X,
                                               const float* __restrict__ W) {
    __shared__ float As[16][68];
    __shared__ float Bs[16][68];
    int t  = threadIdx.x;
    int tx = t & 15, ty = t >> 4;
    int m0 = blockIdx.x * 64, n0 = blockIdx.y * 64;

    float acc[4][4];
    #pragma unroll
    for (int i = 0; i < 4; i++)
        #pragma unroll
        for (int j = 0; j < 4; j++) acc[i][j] = 0.f;

    for (int k0 = 0; k0 < DIN; k0 += 16) {
        {
            int row = t >> 2, c4 = (t & 3) * 4;
            float4 v = *(const float4*)&X[(size_t)(m0 + row) * DIN + k0 + c4];
            As[c4 + 0][row] = v.x; As[c4 + 1][row] = v.y;
            As[c4 + 2][row] = v.z; As[c4 + 3][row] = v.w;
        }
        {
            int row = t >> 4, c4 = (t & 15) * 4;
            *(float4*)&Bs[row][c4] = *(const float4*)&W[(size_t)(k0 + row) * DOUT + n0 + c4];
        }
        __syncthreads();
        #pragma unroll
        for (int k = 0; k < 16; k++) {
            float4 a4 = *(float4*)&As[k][ty * 4];
            float4 b4 = *(float4*)&Bs[k][tx * 4];
            float av[4] = {a4.x, a4.y, a4.z, a4.w};
            float bv[4] = {b4.x, b4.y, b4.z, b4.w};
            #pragma unroll
            for (int i = 0; i < 4; i++)
                #pragma unroll
                for (int j = 0; j < 4; j++) acc[i][j] += av[i] * bv[j];
        }
        __syncthreads();
    }
    #pragma unroll
    for (int i = 0; i < 4; i++) {
        float4 v = make_float4(acc[i][0], acc[i][1], acc[i][2], acc[i][3]);
        *(float4*)&g_Wh[(size_t)(m0 + ty * 4 + i) * DOUT + n0 + tx * 4] = v;
    }
    #pragma unroll
    for (int i = 0; i < 4; i++)
        #pragma unroll
        for (int j = 0; j < 4; j++) {
            int m = m0 + ty * 4 + i;          // node (k-dim of k4 GEMM)
            int n = n0 + tx * 4 + j;          // DOUT col
            int jq = n >> 6, kt = m >> 5, kk = (m & 31) >> 3;
            int ntile = (n & 63) >> 3;
            int lane  = ((n & 7) << 2) | (m & 3);
            int reg   = (m & 4) >> 2;
            size_t idx = ((size_t)(((jq * 256 + kt) * 4 + kk) * 8 + ntile)) * 64
                         + lane * 2 + reg;
            g_WhB[idx] = f2tf32(acc[i][j]);
        }
}

// ---------------- K2: src/dst projections (warp per row) ---------------------
__global__ void __launch_bounds__(256) k2_srcdst(const float* __restrict__ a) {
    int lane = threadIdx.x & 31, w = threadIdx.x >> 5;
    int i = blockIdx.x * 8 + w;
    float s1 = 0.f, s2 = 0.f;
    #pragma unroll
    for (int c = lane; c < DOUT; c += 32) {
        float wh = g_Wh[(size_t)i * DOUT + c];
        s1 += wh * a[c];
        s2 += wh * a[DOUT + c];
    }
    #pragma unroll
    for (int o = 16; o > 0; o >>= 1) {
        s1 += __shfl_xor_sync(0xffffffffu, s1, o);
        s2 += __shfl_xor_sync(0xffffffffu, s2, o);
    }
    if (lane == 0) { g_src[i] = s1; g_dst[i] = s2; }
}

// ---------------- K3: per-row max and sum(exp(e - m)) ------------------------
__global__ void __launch_bounds__(256) k3_rowstats(const int* __restrict__ adj) {
    int i = blockIdx.x;
    int t = threadIdx.x;
    int lane = t & 31, w = t >> 5;
    __shared__ float red[8];
    __shared__ float bcast;

    float si = g_src[i];
    float ev[32];
    float mx = NEG_INF;
    #pragma unroll
    for (int s = 0; s < 8; s++) {
        int j = (s * 256 + t) * 4;
        int4   a4 = *(const int4*)&adj[(size_t)i * N_NODES + j];
        float4 d4 = *(const float4*)&g_dst[j];
        float xs[4] = {si + d4.x, si + d4.y, si + d4.z, si + d4.w};
        int   am[4] = {a4.x, a4.y, a4.z, a4.w};
        #pragma unroll
        for (int c = 0; c < 4; c++) {
            float x = xs[c];
            float e = x > 0.f ? x : ALPHA * x;
            e = (am[c] > 0) ? e : NEG_INF;
            ev[s * 4 + c] = e;
            mx = fmaxf(mx, e);
        }
    }
    #pragma unroll
    for (int o = 16; o > 0; o >>= 1) mx = fmaxf(mx, __shfl_xor_sync(0xffffffffu, mx, o));
    if (lane == 0) red[w] = mx;
    __syncthreads();
    if (t == 0) {
        float m2 = red[0];
        #pragma unroll
        for (int q = 1; q < 8; q++) m2 = fmaxf(m2, red[q]);
        bcast = m2;
    }
    __syncthreads();
    float bm = bcast;

    float sum = 0.f;
    #pragma unroll
    for (int q = 0; q < 32; q++) sum += __expf(ev[q] - bm);
    #pragma unroll
    for (int o = 16; o > 0; o >>= 1) sum += __shfl_xor_sync(0xffffffffu, sum, o);
    __syncthreads();
    if (lane == 0) red[w] = sum;
    __syncthreads();
    if (t == 0) {
        float s2 = 0.f;
        #pragma unroll
        for (int q = 0; q < 8; q++) s2 += red[q];
        g_rmax[i] = bm;
        g_rsum[i] = s2;
    }
}

// ---------------- K4: h' = softmax(P) @ Wh, fragment-layout tf32 MMA ---------
// Grid (64, 4): x = 128-row tile, y = 64-col quarter. Block 512 (16 warps, 4x4).
// P built straight into A-fragment layout; Wh cp.async'd from pre-packed
// B-fragment global. Double-buffered, one barrier per 32-k tile.
#define KT          32
#define NIT         (N_NODES / KT)
#define PBLK        132                   // words per (kk, mtile) block (128 + 4 pad)
#define P_STAGE_W   (4 * 8 * PBLK)        // 4224 words
#define WH_STAGE_W  2048                  // words
#define WH_OFF      0
#define P_OFF       (2 * WH_STAGE_W * 4)              // 16384 B
#define STATS_OFF   (P_OFF + 2 * P_STAGE_W * 4)       // 50176 B
#define SMEM_K4     (STATS_OFF + 3 * 128 * 4)         // 51712 B

__global__ void __launch_bounds__(512, 2) k4_attn(const int* __restrict__ adj,
                                                  float* __restrict__ out) {
    extern __shared__ uint32_t smem[];
    uint32_t* whs = smem;                                 // [2][2048]
    uint32_t* ps  = smem + 2 * WH_STAGE_W;                // [2][4224]
    float* src_s  = (float*)(smem + (STATS_OFF >> 2));    // [128]
    float* m2_s   = src_s + 128;                          // m * log2e
    float* linv_s = src_s + 256;

    int t    = threadIdx.x;
    int lane = t & 31, w = t >> 5;
    int wm = w & 3;            // 32-row quarter of 128
    int wn = w >> 2;           // 16-col quarter of 64
    int I0 = blockIdx.x * 128;
    int J0 = blockIdx.y * 64;
    int jq = blockIdx.y;

    if (t < 128) {
        src_s[t]  = g_src[I0 + t];
        m2_s[t]   = g_rmax[I0 + t] * L2E;
        linv_s[t] = 1.0f / g_rsum[I0 + t];
    }

    float acc[2][2][4];
    #pragma unroll
    for (int ma = 0; ma < 2; ma++)
        #pragma unroll
        for (int na = 0; na < 2; na++)
            #pragma unroll
            for (int q = 0; q < 4; q++) acc[ma][na][q] = 0.f;

    // builder mapping: rows rb, rb+64; cols kc..kc+3
    int rb = t >> 3;
    int kc = (t & 7) * 4;
    int kkb   = kc >> 3;                       // kk of built values
    int khalf = (kc & 4) >> 1;                 // reg bit 1

    // ---- prologue ----
    int4   adjr[2];
    float4 dvr;
    adjr[0] = *(const int4*)&adj[(size_t)(I0 + rb)      * N_NODES + kc];
    adjr[1] = *(const int4*)&adj[(size_t)(I0 + rb + 64) * N_NODES + kc];
    dvr     = *(const float4*)&g_dst[kc];

    // Wh stage 0: contiguous 8KB, one 16B cp.async per thread
    cp_async16((uint32_t)__cvta_generic_to_shared(&whs[t * 4]),
               &g_WhB[(size_t)(jq * 256 + 0) * 2048 + t * 4]);
    cp_commit();

    __syncthreads();   // stats visible for P build

    // build P stage 0 (A-fragment layout)
    #pragma unroll
    for (int si = 0; si < 2; si++) {
        int r = rb + si * 64;
        float sv = src_s[r], mt = m2_s[r];
        float xs[4] = {sv + dvr.x, sv + dvr.y, sv + dvr.z, sv + dvr.w};
        int   am[4] = {adjr[si].x, adjr[si].y, adjr[si].z, adjr[si].w};
        int base = (kkb * 8 + (r >> 4)) * PBLK + ((r & 7) << 4)
                 + (((r & 8) >> 3) | khalf);
        #pragma unroll
        for (int c = 0; c < 4; c++) {
            float x = xs[c];
            float e = x > 0.f ? x : ALPHA * x;
            e = (am[c] > 0) ? e : NEG_INF;
            ps[base + c * 4] = f2tf32(exp2f(fmaf(e, L2E, -mt)));
        }
    }

    // prefetch tile 1 adj/dst
    adjr[0] = *(const int4*)&adj[(size_t)(I0 + rb)      * N_NODES + KT + kc];
    adjr[1] = *(const int4*)&adj[(size_t)(I0 + rb + 64) * N_NODES + KT + kc];
    dvr     = *(const float4*)&g_dst[KT + kc];

    for (int it = 0; it < NIT; ++it) {
        int cur  = it & 1;
        int nxt  = cur ^ 1;
        bool more = (it + 1 < NIT);

        cp_wait<0>();
        __syncthreads();   // publishes stage cur; retires all reads of nxt

        if (more) {
            int kn = (it + 1) * KT;
            // Wh[nxt] cp.async (contiguous)
            cp_async16((uint32_t)__cvta_generic_to_shared(
                           &whs[nxt * WH_STAGE_W + t * 4]),
                       &g_WhB[(size_t)(jq * 256 + (it + 1)) * 2048 + t * 4]);
            cp_commit();

            // build P[nxt] from prefetched regs
            uint32_t* Pn = ps + nxt * P_STAGE_W;
            #pragma unroll
            for (int si = 0; si < 2; si++) {
                int r = rb + si * 64;
                float sv = src_s[r], mt = m2_s[r];
                float xs[4] = {sv + dvr.x, sv + dvr.y, sv + dvr.z, sv + dvr.w};
                int   am[4] = {adjr[si].x, adjr[si].y, adjr[si].z, adjr[si].w};
                int base = (kkb * 8 + (r >> 4)) * PBLK + ((r & 7) << 4)
                         + (((r & 8) >> 3) | khalf);
                #pragma unroll
                for (int c = 0; c < 4; c++) {
                    float x = xs[c];
                    float e = x > 0.f ? x : ALPHA * x;
                    e = (am[c] > 0) ? e : NEG_INF;
                    Pn[base + c * 4] = f2tf32(exp2f(fmaf(e, L2E, -mt)));
                }
            }

            // prefetch adj/dst for tile it+2
            if (it + 2 < NIT) {
                int kn2 = kn + KT;
                adjr[0] = *(const int4*)&adj[(size_t)(I0 + rb)      * N_NODES + kn2 + kc];
                adjr[1] = *(const int4*)&adj[(size_t)(I0 + rb + 64) * N_NODES + kn2 + kc];
                dvr     = *(const float4*)&g_dst[kn2 + kc];
            }
        }

        // ---- MMAs on stage cur ----
        {
            const uint32_t* Pc = ps  + cur * P_STAGE_W;
            const uint32_t* Wc = whs + cur * WH_STAGE_W;
            #pragma unroll
            for (int kk = 0; kk < 4; kk++) {
                uint2 b[2];
                #pragma unroll
                for (int na = 0; na < 2; na++)
                    b[na] = *(const uint2*)&Wc[(kk * 8 + wn * 2 + na) * 64 + lane * 2];
                #pragma unroll
                for (int ma = 0; ma < 2; ma++) {
                    uint4 af = *(const uint4*)&Pc[(kk * 8 + wm * 2 + ma) * PBLK + lane * 4];
                    #pragma unroll
                    for (int na = 0; na < 2; na++)
                        mma_tf32(acc[ma][na], af.x, af.y, af.z, af.w, b[na].x, b[na].y);
                }
            }
        }
    }

    // ---- epilogue: /rowsum, ELU, store (float2) ----
    #pragma unroll
    for (int ma = 0; ma < 2; ma++) {
        int r0 = wm * 32 + ma * 16 + (lane >> 2);
        #pragma unroll
        for (int na = 0; na < 2; na++) {
            int c = J0 + wn * 16 + na * 8 + (lane & 3) * 2;
            #pragma unroll
            for (int qh = 0; qh < 2; qh++) {
                int r = r0 + qh * 8;
                float li = linv_s[r];
                float v0 = acc[ma][na][qh * 2 + 0] * li;
                float v1 = acc[ma][na][qh * 2 + 1] * li;
                float2 v;
                v.x = (v0 > 0.f) ? v0 : expm1f(v0);
                v.y = (v1 > 0.f) ? v1 : expm1f(v1);
                *(float2*)&out[(size_t)(I0 + r) * DOUT + c] = v;
            }
        }
    }
}

// ---------------- launch ------------------------------------------------------
extern "C" void kernel_launch(void* const* d_in, const int* in_sizes, int n_in,
                              void* d_out, int out_size) {
    const float* X   = (const float*)d_in[0];   // features [8192,512]
    const int*   adj = (const int*)  d_in[1];   // adj      [8192,8192]
    const float* W   = (const float*)d_in[2];   // W        [512,256]
    const float* a   = (const float*)d_in[3];   // a        [512,1]
    float* out = (float*)d_out;                 // [8192,256]

    static bool attr_done = false;
    if (!attr_done) {
        cudaFuncSetAttribute(k4_attn, cudaFuncAttributeMaxDynamicSharedMemorySize,
                             SMEM_K4);
        attr_done = true;
    }

    k1_gemm    <<<dim3(N_NODES / 64, DOUT / 64), 256>>>(X, W);
    k2_srcdst  <<<N_NODES / 8, 256>>>(a);
    k3_rowstats<<<N_NODES, 256>>>(adj);
    k4_attn    <<<dim3(N_NODES / 128, 4), 512, SMEM_K4>>>(adj, out);
}

// round 7
// speedup vs baseline: 1.1312x; 1.1312x over previous
#include <cuda_runtime.h>
#include <cstdint>
#include <cstddef>

#define N_NODES 8192
#define DIN     512
#define DOUT    256
#define ALPHA   0.2f
#define NEG_INF -9e15f
#define L2E     1.4426950408889634f

// ---------------- scratch (device globals; no allocations allowed) ----------
__device__ float    g_Wh [(size_t)N_NODES * DOUT];   // 8 MB fp32 row-major (k2)
__device__ uint32_t g_WhA[(size_t)DOUT * N_NODES];   // 8 MB tf32, A-fragment order (k4)
__device__ float g_src[N_NODES];
__device__ float g_dst[N_NODES];
__device__ float g_rmax[N_NODES];
__device__ float g_rsum[N_NODES];

// ---------------- helpers ----------------------------------------------------
__device__ __forceinline__ uint32_t f2tf32(float x) {
    uint32_t r;
    asm("cvt.rna.tf32.f32 %0, %1;" : "=r"(r) : "f"(x));
    return r;
}

__device__ __forceinline__ void mma_tf32(float* c,
                                         uint32_t a0, uint32_t a1, uint32_t a2, uint32_t a3,
                                         uint32_t b0, uint32_t b1) {
    asm volatile(
        "mma.sync.aligned.m16n8k8.row.col.f32.tf32.tf32.f32 "
        "{%0,%1,%2,%3}, {%4,%5,%6,%7}, {%8,%9}, {%0,%1,%2,%3};\n"
        : "+f"(c[0]), "+f"(c[1]), "+f"(c[2]), "+f"(c[3])
        : "r"(a0), "r"(a1), "r"(a2), "r"(a3), "r"(b0), "r"(b1));
}

__device__ __forceinline__ void cp_async16(uint32_t smem_addr, const void* gptr) {
    asm volatile("cp.async.cg.shared.global [%0], [%1], 16;\n"
                 :: "r"(smem_addr), "l"(gptr));
}
__device__ __forceinline__ void cp_commit() {
    asm volatile("cp.async.commit_group;\n" ::: "memory");
}
template <int N>
__device__ __forceinline__ void cp_wait() {
    asm volatile("cp.async.wait_group %0;\n" :: "n"(N) : "memory");
}

// ---------------- K1: Wh = X @ W  (fp32, tiled) ------------------------------
// Emits g_WhA: tf32 bits packed in exact m16k8 A-fragment order for k4.
// Value (node m, dout n): td=n>>6, it=m>>5, kk=(m&31)>>3, mt=(n&63)>>4,
// lane=(((n&63)&7)<<2)|(m&3), reg=((n>>3)&1)|(((m>>2)&1)<<1)
__global__ void __launch_bounds__(256) k1_gemm(const float* __restrict__ X,
                                               const float* __restrict__ W) {
    __shared__ float As[16][68];
    __shared__ float Bs[16][68];
    int t  = threadIdx.x;
    int tx = t & 15, ty = t >> 4;
    int m0 = blockIdx.x * 64, n0 = blockIdx.y * 64;

    float acc[4][4];
    #pragma unroll
    for (int i = 0; i < 4; i++)
        #pragma unroll
        for (int j = 0; j < 4; j++) acc[i][j] = 0.f;

    for (int k0 = 0; k0 < DIN; k0 += 16) {
        {
            int row = t >> 2, c4 = (t & 3) * 4;
            float4 v = *(const float4*)&X[(size_t)(m0 + row) * DIN + k0 + c4];
            As[c4 + 0][row] = v.x; As[c4 + 1][row] = v.y;
            As[c4 + 2][row] = v.z; As[c4 + 3][row] = v.w;
        }
        {
            int row = t >> 4, c4 = (t & 15) * 4;
            *(float4*)&Bs[row][c4] = *(const float4*)&W[(size_t)(k0 + row) * DOUT + n0 + c4];
        }
        __syncthreads();
        #pragma unroll
        for (int k = 0; k < 16; k++) {
            float4 a4 = *(float4*)&As[k][ty * 4];
            float4 b4 = *(float4*)&Bs[k][tx * 4];
            float av[4] = {a4.x, a4.y, a4.z, a4.w};
            float bv[4] = {b4.x, b4.y, b4.z, b4.w};
            #pragma unroll
            for (int i = 0; i < 4; i++)
                #pragma unroll
                for (int j = 0; j < 4; j++) acc[i][j] += av[i] * bv[j];
        }
        __syncthreads();
    }
    #pragma unroll
    for (int i = 0; i < 4; i++) {
        float4 v = make_float4(acc[i][0], acc[i][1], acc[i][2], acc[i][3]);
        *(float4*)&g_Wh[(size_t)(m0 + ty * 4 + i) * DOUT + n0 + tx * 4] = v;
    }
    #pragma unroll
    for (int i = 0; i < 4; i++)
        #pragma unroll
        for (int j = 0; j < 4; j++) {
            int m = m0 + ty * 4 + i;          // node  (k-dim of k4 GEMM)
            int n = n0 + tx * 4 + j;          // dout  (m-dim of k4 GEMM)
            int td = n >> 6, itl = m >> 5;
            int kloc = m & 31, dloc = n & 63;
            int kk = kloc >> 3, mtA = dloc >> 4;
            int laneA = ((dloc & 7) << 2) | (kloc & 3);
            int reg = ((dloc >> 3) & 1) | (((kloc >> 2) & 1) << 1);
            g_WhA[((size_t)(td * 256 + itl)) * 2048 + (kk * 4 + mtA) * 128
                  + laneA * 4 + reg] = f2tf32(acc[i][j]);
        }
}

// ---------------- K2: src/dst projections (warp per row) ---------------------
__global__ void __launch_bounds__(256) k2_srcdst(const float* __restrict__ a) {
    int lane = threadIdx.x & 31, w = threadIdx.x >> 5;
    int i = blockIdx.x * 8 + w;
    float s1 = 0.f, s2 = 0.f;
    #pragma unroll
    for (int c = lane; c < DOUT; c += 32) {
        float wh = g_Wh[(size_t)i * DOUT + c];
        s1 += wh * a[c];
        s2 += wh * a[DOUT + c];
    }
    #pragma unroll
    for (int o = 16; o > 0; o >>= 1) {
        s1 += __shfl_xor_sync(0xffffffffu, s1, o);
        s2 += __shfl_xor_sync(0xffffffffu, s2, o);
    }
    if (lane == 0) { g_src[i] = s1; g_dst[i] = s2; }
}

// ---------------- K3: per-row max and sum(exp(e - m)) ------------------------
__global__ void __launch_bounds__(256) k3_rowstats(const int* __restrict__ adj) {
    int i = blockIdx.x;
    int t = threadIdx.x;
    int lane = t & 31, w = t >> 5;
    __shared__ float red[8];
    __shared__ float bcast;

    float si = g_src[i];
    float ev[32];
    float mx = NEG_INF;
    #pragma unroll
    for (int s = 0; s < 8; s++) {
        int j = (s * 256 + t) * 4;
        int4   a4 = *(const int4*)&adj[(size_t)i * N_NODES + j];
        float4 d4 = *(const float4*)&g_dst[j];
        float xs[4] = {si + d4.x, si + d4.y, si + d4.z, si + d4.w};
        int   am[4] = {a4.x, a4.y, a4.z, a4.w};
        #pragma unroll
        for (int c = 0; c < 4; c++) {
            float x = xs[c];
            float e = fmaxf(x, ALPHA * x);
            e = (am[c] > 0) ? e : NEG_INF;
            ev[s * 4 + c] = e;
            mx = fmaxf(mx, e);
        }
    }
    #pragma unroll
    for (int o = 16; o > 0; o >>= 1) mx = fmaxf(mx, __shfl_xor_sync(0xffffffffu, mx, o));
    if (lane == 0) red[w] = mx;
    __syncthreads();
    if (t == 0) {
        float m2 = red[0];
        #pragma unroll
        for (int q = 1; q < 8; q++) m2 = fmaxf(m2, red[q]);
        bcast = m2;
    }
    __syncthreads();
    float bm = bcast;

    float sum = 0.f;
    #pragma unroll
    for (int q = 0; q < 32; q++) sum += __expf(ev[q] - bm);
    #pragma unroll
    for (int o = 16; o > 0; o >>= 1) sum += __shfl_xor_sync(0xffffffffu, sum, o);
    __syncthreads();
    if (lane == 0) red[w] = sum;
    __syncthreads();
    if (t == 0) {
        float s2 = 0.f;
        #pragma unroll
        for (int q = 0; q < 8; q++) s2 += red[q];
        g_rmax[i] = bm;
        g_rsum[i] = s2;
    }
}

// ---------------- K4: out^T = Wh^T @ P^T, swapped-operand tf32 MMA -----------
// Grid (64, 4): bx -> 128-node i-tile, by -> 64-col d-tile. Block 256 (8 warps:
// wn = w&3 over 32-i quarters, kh = w>>2 over 16-k halves). A = WhA (fragment-
// packed, cp.async), B = P (pair-interleaved + XOR swizzle, built on the fly).
// B-frag duplication 1x, A-frag 4x; everything LDS.64/LDS.128/STS.64.
#define KT        32
#define NIT       (N_NODES / KT)
#define PSTRIDE   40
#define A_OFF_W   0          // [2][2048]
#define P_OFF_W   4096       // [2][5120]
#define DST_OFF_W 14336      // [2][32]
#define STAT_OFF_W 14400     // src 128, m2 128, linv 128
#define SMEM_K4   ((14400 + 384) * 4)

__global__ void __launch_bounds__(256, 2) k4_attn(const int* __restrict__ adj,
                                                  float* __restrict__ out) {
    extern __shared__ uint32_t smem[];
    uint32_t* whs   = smem + A_OFF_W;
    uint32_t* ps    = smem + P_OFF_W;
    float*    dst_s = (float*)(smem + DST_OFF_W);
    float*    src_s = (float*)(smem + STAT_OFF_W);
    float*    m2_s  = src_s + 128;
    float*    linv_s = src_s + 256;

    int t    = threadIdx.x;
    int lane = t & 31, w = t >> 5;
    int wn = w & 3;          // 32-i quarter
    int kh = w >> 2;         // 16-k half
    int I0 = blockIdx.x * 128;
    int J0 = blockIdx.y * 64;
    int by = blockIdx.y;

    if (t < 128) {
        src_s[t]  = g_src[I0 + t];
        m2_s[t]   = g_rmax[I0 + t] * L2E;
        linv_s[t] = 1.0f / g_rsum[I0 + t];
    }

    float acc[4][4][4];
    #pragma unroll
    for (int mt = 0; mt < 4; mt++)
        #pragma unroll
        for (int na = 0; na < 4; na++)
            #pragma unroll
            for (int q = 0; q < 4; q++) acc[mt][na][q] = 0.f;

    // builder mapping: one row, 16 k per thread
    int rB = t >> 1;                 // 0..127
    int q0 = t & 1;                  // which 16-k half
    const int* adjrow = adj + (size_t)(I0 + rB) * N_NODES + q0 * 16;

    // ---- prologue: A[0], dst[0], dst[1] cp.async; adj tile0 regs ----
    {
        uint32_t sa = (uint32_t)__cvta_generic_to_shared(&whs[t * 8]);
        const uint32_t* g = &g_WhA[((size_t)(by * 256 + 0)) * 2048 + t * 8];
        cp_async16(sa, g);
        cp_async16(sa + 16, g + 4);
        if (t < 8)
            cp_async16((uint32_t)__cvta_generic_to_shared(&dst_s[t * 4]),
                       &g_dst[t * 4]);
        else if (t < 16)
            cp_async16((uint32_t)__cvta_generic_to_shared(&dst_s[32 + (t - 8) * 4]),
                       &g_dst[KT + (t - 8) * 4]);
        cp_commit();
    }
    int4 a0 = *(const int4*)&adjrow[0];
    int4 a1 = *(const int4*)&adjrow[4];
    int4 a2 = *(const int4*)&adjrow[8];
    int4 a3 = *(const int4*)&adjrow[12];

    cp_wait<0>();
    __syncthreads();     // stats + dst[0] visible

    // build P[0]
    {
        float sv = src_s[rB], mt2 = m2_s[rB];
        uint32_t* Pr = ps + rB * PSTRIDE;
        const float* dv = &dst_s[0 * 32 + q0 * 16];
        int rs3 = rB & 3, rs4 = (rB >> 2) & 1;
        #pragma unroll
        for (int qi = 0; qi < 2; qi++) {
            int q = q0 * 2 + qi;
            int physq = q ^ rs4;
            float4 dl = *(const float4*)&dv[qi * 8];
            float4 dh = *(const float4*)&dv[qi * 8 + 4];
            int4 al = (qi == 0) ? a0 : a2;
            int4 ah = (qi == 0) ? a1 : a3;
            float xl[4] = {sv + dl.x, sv + dl.y, sv + dl.z, sv + dl.w};
            float xh[4] = {sv + dh.x, sv + dh.y, sv + dh.z, sv + dh.w};
            int ml[4] = {al.x, al.y, al.z, al.w};
            int mh[4] = {ah.x, ah.y, ah.z, ah.w};
            #pragma unroll
            for (int tp = 0; tp < 4; tp++) {
                float el = fmaxf(xl[tp], ALPHA * xl[tp]);
                el = (ml[tp] > 0) ? el : NEG_INF;
                float eh = fmaxf(xh[tp], ALPHA * xh[tp]);
                eh = (mh[tp] > 0) ? eh : NEG_INF;
                uint2 pw;
                pw.x = f2tf32(exp2f(fmaf(el, L2E, -mt2)));
                pw.y = f2tf32(exp2f(fmaf(eh, L2E, -mt2)));
                *(uint2*)&Pr[physq * 8 + (tp ^ rs3) * 2] = pw;
            }
        }
    }
    // prefetch adj tile 1
    a0 = *(const int4*)&adjrow[KT];
    a1 = *(const int4*)&adjrow[KT + 4];
    a2 = *(const int4*)&adjrow[KT + 8];
    a3 = *(const int4*)&adjrow[KT + 12];

    for (int it = 0; it < NIT; ++it) {
        int cur = it & 1;
        int nxt = cur ^ 1;
        bool more = (it + 1 < NIT);

        if (it) cp_wait<0>();
        __syncthreads();   // publishes A[cur] + P[cur] + dst[nxt]; retires reads of nxt

        if (more) {
            // A[nxt] cp.async (contiguous fragment-packed 8KB)
            uint32_t sa = (uint32_t)__cvta_generic_to_shared(&whs[nxt * 2048 + t * 8]);
            const uint32_t* g = &g_WhA[((size_t)(by * 256 + it + 1)) * 2048 + t * 8];
            cp_async16(sa, g);
            cp_async16(sa + 16, g + 4);
            // dst for tile it+2 into slot (it+2)&1 == cur
            if (it + 2 < NIT && t < 8)
                cp_async16((uint32_t)__cvta_generic_to_shared(&dst_s[cur * 32 + t * 4]),
                           &g_dst[(it + 2) * KT + t * 4]);
            cp_commit();

            // build P[nxt] (tile it+1) from prefetched adj + dst_s[nxt]
            {
                float sv = src_s[rB], mt2 = m2_s[rB];
                uint32_t* Pr = ps + nxt * 5120 + rB * PSTRIDE;
                const float* dv = &dst_s[nxt * 32 + q0 * 16];
                int rs3 = rB & 3, rs4 = (rB >> 2) & 1;
                #pragma unroll
                for (int qi = 0; qi < 2; qi++) {
                    int q = q0 * 2 + qi;
                    int physq = q ^ rs4;
                    float4 dl = *(const float4*)&dv[qi * 8];
                    float4 dh = *(const float4*)&dv[qi * 8 + 4];
                    int4 al = (qi == 0) ? a0 : a2;
                    int4 ah = (qi == 0) ? a1 : a3;
                    float xl[4] = {sv + dl.x, sv + dl.y, sv + dl.z, sv + dl.w};
                    float xh[4] = {sv + dh.x, sv + dh.y, sv + dh.z, sv + dh.w};
                    int ml[4] = {al.x, al.y, al.z, al.w};
                    int mh[4] = {ah.x, ah.y, ah.z, ah.w};
                    #pragma unroll
                    for (int tp = 0; tp < 4; tp++) {
                        float el = fmaxf(xl[tp], ALPHA * xl[tp]);
                        el = (ml[tp] > 0) ? el : NEG_INF;
                        float eh = fmaxf(xh[tp], ALPHA * xh[tp]);
                        eh = (mh[tp] > 0) ? eh : NEG_INF;
                        uint2 pw;
                        pw.x = f2tf32(exp2f(fmaf(el, L2E, -mt2)));
                        pw.y = f2tf32(exp2f(fmaf(eh, L2E, -mt2)));
                        *(uint2*)&Pr[physq * 8 + (tp ^ rs3) * 2] = pw;
                    }
                }
            }

            // prefetch adj for tile it+2
            if (it + 2 < NIT) {
                const int* ab = adjrow + (it + 2) * KT;
                a0 = *(const int4*)&ab[0];
                a1 = *(const int4*)&ab[4];
                a2 = *(const int4*)&ab[8];
                a3 = *(const int4*)&ab[12];
            }
        }

        // ---- MMAs on stage cur (warp covers all 64 d, its 32 i, its 16 k) ----
        {
            const uint32_t* Ac = whs + cur * 2048;
            const uint32_t* Pc = ps  + cur * 5120;
            #pragma unroll
            for (int kki = 0; kki < 2; kki++) {
                int kk = kh * 2 + kki;
                uint2 b[4];
                #pragma unroll
                for (int na = 0; na < 4; na++) {
                    int rb = wn * 32 + na * 8 + (lane >> 2);
                    int addr = rb * PSTRIDE + ((kk ^ ((rb >> 2) & 1)) * 8)
                             + (((lane & 3) ^ (rb & 3)) * 2);
                    b[na] = *(const uint2*)&Pc[addr];
                }
                #pragma unroll
                for (int mt = 0; mt < 4; mt++) {
                    uint4 af = *(const uint4*)&Ac[(kk * 4 + mt) * 128 + lane * 4];
                    #pragma unroll
                    for (int na = 0; na < 4; na++)
                        mma_tf32(acc[mt][na], af.x, af.y, af.z, af.w,
                                 b[na].x, b[na].y);
                }
            }
        }
    }

    // ---- epilogue: cross-kh reduction via smem, then /rowsum + ELU + store ----
    __syncthreads();
    float* red = (float*)(smem + P_OFF_W);     // 32KB scratch (P region)
    if (kh == 1) {
        #pragma unroll
        for (int mt = 0; mt < 4; mt++)
            #pragma unroll
            for (int na = 0; na < 4; na++)
                *(float4*)&red[(((wn * 16) + mt * 4 + na) * 32 + lane) * 4] =
                    *(float4*)acc[mt][na];
    }
    __syncthreads();
    if (kh == 0) {
        int g  = lane >> 2;
        int t2 = (lane & 3) * 2;
        #pragma unroll
        for (int mt = 0; mt < 4; mt++)
            #pragma unroll
            for (int na = 0; na < 4; na++) {
                float4 o = *(float4*)&red[(((wn * 16) + mt * 4 + na) * 32 + lane) * 4];
                float c0 = acc[mt][na][0] + o.x;
                float c1 = acc[mt][na][1] + o.y;
                float c2 = acc[mt][na][2] + o.z;
                float c3 = acc[mt][na][3] + o.w;
                int i0 = wn * 32 + na * 8 + t2;
                int d0 = J0 + mt * 16 + g;
                float l0 = linv_s[i0], l1 = linv_s[i0 + 1];
                c0 *= l0; c1 *= l1; c2 *= l0; c3 *= l1;
                c0 = (c0 > 0.f) ? c0 : expm1f(c0);
                c1 = (c1 > 0.f) ? c1 : expm1f(c1);
                c2 = (c2 > 0.f) ? c2 : expm1f(c2);
                c3 = (c3 > 0.f) ? c3 : expm1f(c3);
                out[(size_t)(I0 + i0)     * DOUT + d0]     = c0;
                out[(size_t)(I0 + i0 + 1) * DOUT + d0]     = c1;
                out[(size_t)(I0 + i0)     * DOUT + d0 + 8] = c2;
                out[(size_t)(I0 + i0 + 1) * DOUT + d0 + 8] = c3;
            }
    }
}

// ---------------- launch ------------------------------------------------------
extern "C" void kernel_launch(void* const* d_in, const int* in_sizes, int n_in,
                              void* d_out, int out_size) {
    const float* X   = (const float*)d_in[0];   // features [8192,512]
    const int*   adj = (const int*)  d_in[1];   // adj      [8192,8192]
    const float* W   = (const float*)d_in[2];   // W        [512,256]
    const float* a   = (const float*)d_in[3];   // a        [512,1]
    float* out = (float*)d_out;                 // [8192,256]

    static bool attr_done = false;
    if (!attr_done) {
        cudaFuncSetAttribute(k4_attn, cudaFuncAttributeMaxDynamicSharedMemorySize,
                             SMEM_K4);
        attr_done = true;
    }

    k1_gemm    <<<dim3(N_NODES / 64, DOUT / 64), 256>>>(X, W);
    k2_srcdst  <<<N_NODES / 8, 256>>>(a);
    k3_rowstats<<<N_NODES, 256>>>(adj);
    k4_attn    <<<dim3(N_NODES / 128, 4), 256, SMEM_K4>>>(adj, out);
}